// round 2
// baseline (speedup 1.0000x reference)
#include <cuda_runtime.h>
#include <cuda_bf16.h>
#include <math.h>

// Problem constants
#define NN 65536
#define DD 2048
#define LD 64          // d
#define SS 32          // s
#define KTRI 2080      // d*(d+1)/2
#define KTOT 96        // d + s

// Scratch: quad = theta^T @ psi, (32 x 65536) fp32 = 8 MB
__device__ float g_quad[(size_t)SS * NN];

__device__ __forceinline__ unsigned f2tf(float x) {
    unsigned y;
    asm("cvt.rna.tf32.f32 %0, %1;" : "=r"(y) : "f"(x));
    return y;
}

__device__ __forceinline__ void mma_tf32(float* c,
                                         unsigned a0, unsigned a1, unsigned a2, unsigned a3,
                                         unsigned b0, unsigned b1) {
    asm volatile(
        "mma.sync.aligned.m16n8k8.row.col.f32.tf32.tf32.f32 "
        "{%0,%1,%2,%3}, {%4,%5,%6,%7}, {%8,%9}, {%0,%1,%2,%3};"
        : "+f"(c[0]), "+f"(c[1]), "+f"(c[2]), "+f"(c[3])
        : "r"(a0), "r"(a1), "r"(a2), "r"(a3), "r"(b0), "r"(b1));
}

// ---------------------------------------------------------------------------
// Kernel 1: quad^T (Ncols x 32) = psi^T (Ncols x 2080) @ theta (2080 x 32)
// psi generated on the fly from a phi tile in smem. CTA = 8 warps x 64 cols.
// ---------------------------------------------------------------------------
#define K1_COLS 512
#define PHI_STRIDE 520     // mod 32 == 8 -> conflict-free fragment reads
#define KC 208             // K chunk (2080 = 10 * 208), 26 k-steps per chunk
#define TH_STRIDE 40       // mod 32 == 8

#define SMEM1_BYTES (((64 * PHI_STRIDE) + (KC * TH_STRIDE)) * 4 + 2 * KTRI)

__global__ __launch_bounds__(256)
void quad_kernel(const float* __restrict__ phi, const float* __restrict__ theta) {
    extern __shared__ float sm1[];
    float* phi_s = sm1;                                    // 64 * 520
    float* th_s  = sm1 + 64 * PHI_STRIDE;                  // 208 * 40 (tf32 bits)
    unsigned char* ii_s = (unsigned char*)(th_s + KC * TH_STRIDE);
    unsigned char* jj_s = ii_s + KTRI;

    const int tid  = threadIdx.x;
    const int lane = tid & 31;
    const int wid  = tid >> 5;
    const int tig  = lane & 3;   // thread in group
    const int grp  = lane >> 2;  // group id
    const int c0   = blockIdx.x * K1_COLS;

    // Build (i,j) index tables for triu ordering
    for (int k = tid; k < KTRI; k += 256) {
        int gi = (int)(64.5f - sqrtf(64.5f * 64.5f - 2.0f * (float)k));
        gi = max(0, min(63, gi));
        while (gi > 0 && (gi * 64 - (gi * (gi - 1)) / 2) > k) --gi;
        while (gi < 63 && ((gi + 1) * 64 - ((gi + 1) * gi) / 2) <= k) ++gi;
        int base = gi * 64 - (gi * (gi - 1)) / 2;
        ii_s[k] = (unsigned char)gi;
        jj_s[k] = (unsigned char)(gi + (k - base));
    }

    // Load phi tile (64 x 512) in fp32 (products rounded to tf32 later)
    for (int idx = tid; idx < 64 * (K1_COLS / 4); idx += 256) {
        int r  = idx / (K1_COLS / 4);
        int c4 = idx % (K1_COLS / 4);
        float4 v = *(const float4*)(phi + (size_t)r * NN + c0 + c4 * 4);
        float* dst = phi_s + r * PHI_STRIDE + c4 * 4;
        dst[0] = v.x; dst[1] = v.y; dst[2] = v.z; dst[3] = v.w;
    }
    __syncthreads();

    float acc[4][4][4];
#pragma unroll
    for (int a = 0; a < 4; a++)
#pragma unroll
        for (int b = 0; b < 4; b++)
#pragma unroll
            for (int q = 0; q < 4; q++) acc[a][b][q] = 0.f;

    const int wcol = wid * 64;

    for (int ch = 0; ch < KTRI / KC; ++ch) {
        const int kb = ch * KC;
        __syncthreads();  // protect th_s from previous chunk's readers
        // Stage theta chunk (208 x 32), converted to tf32
        for (int idx = tid; idx < KC * 8; idx += 256) {
            int r = idx >> 3, c4 = idx & 7;
            float4 v = *(const float4*)(theta + (size_t)(kb + r) * SS + c4 * 4);
            unsigned* dst = (unsigned*)(th_s + r * TH_STRIDE + c4 * 4);
            dst[0] = f2tf(v.x); dst[1] = f2tf(v.y); dst[2] = f2tf(v.z); dst[3] = f2tf(v.w);
        }
        __syncthreads();

        for (int ks = 0; ks < KC / 8; ++ks) {
            const int k0 = ks * 8;
            const int kg = kb + k0 + tig;
            const int i0 = ii_s[kg],     j0 = jj_s[kg];
            const int i1 = ii_s[kg + 4], j1 = jj_s[kg + 4];
            const float* pi0 = phi_s + i0 * PHI_STRIDE;
            const float* pj0 = phi_s + j0 * PHI_STRIDE;
            const float* pi1 = phi_s + i1 * PHI_STRIDE;
            const float* pj1 = phi_s + j1 * PHI_STRIDE;

            unsigned bfr[4][2];
#pragma unroll
            for (int nt = 0; nt < 4; ++nt) {
                int nB = nt * 8 + grp;
                bfr[nt][0] = __float_as_uint(th_s[(k0 + tig) * TH_STRIDE + nB]);
                bfr[nt][1] = __float_as_uint(th_s[(k0 + tig + 4) * TH_STRIDE + nB]);
            }
#pragma unroll
            for (int mt = 0; mt < 4; ++mt) {
                int col = wcol + mt * 16 + grp;
                unsigned a0 = f2tf(pi0[col]     * pj0[col]);
                unsigned a1 = f2tf(pi0[col + 8] * pj0[col + 8]);
                unsigned a2 = f2tf(pi1[col]     * pj1[col]);
                unsigned a3 = f2tf(pi1[col + 8] * pj1[col + 8]);
#pragma unroll
                for (int nt = 0; nt < 4; ++nt)
                    mma_tf32(acc[mt][nt], a0, a1, a2, a3, bfr[nt][0], bfr[nt][1]);
            }
        }
    }

    // Epilogue: C[col_local][r] -> g_quad[r][col_global]
#pragma unroll
    for (int mt = 0; mt < 4; ++mt) {
        int colg = c0 + wcol + mt * 16 + grp;
#pragma unroll
        for (int nt = 0; nt < 4; ++nt) {
            int r = nt * 8 + 2 * tig;
            g_quad[(size_t)r       * NN + colg]     = acc[mt][nt][0];
            g_quad[(size_t)(r + 1) * NN + colg]     = acc[mt][nt][1];
            g_quad[(size_t)r       * NN + colg + 8] = acc[mt][nt][2];
            g_quad[(size_t)(r + 1) * NN + colg + 8] = acc[mt][nt][3];
        }
    }
}

// ---------------------------------------------------------------------------
// Kernel 2: out (2048 x 65536) = c + Q (2048 x 96) @ z (96 x 65536)
// z rows 0..63 = phi, rows 64..95 = g_quad. CTA tile 128x128, K=96 one-shot.
// ---------------------------------------------------------------------------
#define QS_STRIDE 100   // mod 32 == 4 -> conflict-free A reads
#define BS_STRIDE 136   // mod 32 == 8 -> conflict-free B reads
#define SMEM2_BYTES ((128 * QS_STRIDE + KTOT * BS_STRIDE) * 4)

__global__ __launch_bounds__(256, 2)
void gemm_kernel(const float* __restrict__ cvec, const float* __restrict__ Q,
                 const float* __restrict__ phi, float* __restrict__ out) {
    extern __shared__ float sm2[];
    float* Qs = sm2;                       // 128 x 100 (tf32 bits)
    float* Bs = sm2 + 128 * QS_STRIDE;     // 96 x 136  (tf32 bits)

    const int tid  = threadIdx.x;
    const int lane = tid & 31;
    const int wid  = tid >> 5;
    const int tig  = lane & 3;
    const int grp  = lane >> 2;
    const int wm   = wid & 3;   // 4 warps along M
    const int wn   = wid >> 2;  // 2 warps along N
    const int m0   = blockIdx.x * 128;  // 16 m-tiles (fast dim -> z L2 reuse)
    const int n0   = blockIdx.y * 128;  // 512 n-tiles

    // Stage Q tile (128 x 96) as tf32
    for (int idx = tid; idx < 128 * 24; idx += 256) {
        int m = idx / 24, c4 = idx % 24;
        float4 v = *(const float4*)(Q + (size_t)(m0 + m) * KTOT + c4 * 4);
        unsigned* dst = (unsigned*)(Qs + m * QS_STRIDE + c4 * 4);
        dst[0] = f2tf(v.x); dst[1] = f2tf(v.y); dst[2] = f2tf(v.z); dst[3] = f2tf(v.w);
    }
    // Stage B tile (96 x 128): k<64 from phi, k>=64 from g_quad
    for (int idx = tid; idx < KTOT * 32; idx += 256) {
        int k = idx >> 5, c4 = idx & 31;
        const float* src = (k < LD) ? (phi + (size_t)k * NN)
                                    : (g_quad + (size_t)(k - LD) * NN);
        float4 v = *(const float4*)(src + n0 + c4 * 4);
        unsigned* dst = (unsigned*)(Bs + k * BS_STRIDE + c4 * 4);
        dst[0] = f2tf(v.x); dst[1] = f2tf(v.y); dst[2] = f2tf(v.z); dst[3] = f2tf(v.w);
    }
    __syncthreads();

    float acc[2][8][4];
#pragma unroll
    for (int a = 0; a < 2; a++)
#pragma unroll
        for (int b = 0; b < 8; b++)
#pragma unroll
            for (int q = 0; q < 4; q++) acc[a][b][q] = 0.f;

#pragma unroll
    for (int ks = 0; ks < 12; ++ks) {
        const int k0 = ks * 8;
        unsigned afr[2][4];
#pragma unroll
        for (int mt = 0; mt < 2; ++mt) {
            int row = wm * 32 + mt * 16 + grp;
            afr[mt][0] = __float_as_uint(Qs[row * QS_STRIDE + k0 + tig]);
            afr[mt][1] = __float_as_uint(Qs[(row + 8) * QS_STRIDE + k0 + tig]);
            afr[mt][2] = __float_as_uint(Qs[row * QS_STRIDE + k0 + tig + 4]);
            afr[mt][3] = __float_as_uint(Qs[(row + 8) * QS_STRIDE + k0 + tig + 4]);
        }
#pragma unroll
        for (int nt = 0; nt < 8; ++nt) {
            int coln = wn * 64 + nt * 8 + grp;
            unsigned b0 = __float_as_uint(Bs[(k0 + tig) * BS_STRIDE + coln]);
            unsigned b1 = __float_as_uint(Bs[(k0 + tig + 4) * BS_STRIDE + coln]);
#pragma unroll
            for (int mt = 0; mt < 2; ++mt)
                mma_tf32(acc[mt][nt], afr[mt][0], afr[mt][1], afr[mt][2], afr[mt][3], b0, b1);
        }
    }

    // Epilogue: add c[m], write fp32
#pragma unroll
    for (int mt = 0; mt < 2; ++mt) {
        int rowg = m0 + wm * 32 + mt * 16 + grp;
        float cA = __ldg(cvec + rowg);
        float cB = __ldg(cvec + rowg + 8);
#pragma unroll
        for (int nt = 0; nt < 8; ++nt) {
            int colg = n0 + wn * 64 + nt * 8 + 2 * tig;
            float2 v0 = make_float2(acc[mt][nt][0] + cA, acc[mt][nt][1] + cA);
            float2 v1 = make_float2(acc[mt][nt][2] + cB, acc[mt][nt][3] + cB);
            *(float2*)(out + (size_t)rowg * NN + colg)       = v0;
            *(float2*)(out + (size_t)(rowg + 8) * NN + colg) = v1;
        }
    }
}

// ---------------------------------------------------------------------------
extern "C" void kernel_launch(void* const* d_in, const int* in_sizes, int n_in,
                              void* d_out, int out_size) {
    const float* c     = (const float*)d_in[0];   // (2048, 1)
    const float* Q     = (const float*)d_in[1];   // (2048, 96)
    const float* phi   = (const float*)d_in[2];   // (64, 65536)
    const float* theta = (const float*)d_in[3];   // (2080, 32)
    float* out = (float*)d_out;                   // (2048, 65536)

    cudaFuncSetAttribute(quad_kernel, cudaFuncAttributeMaxDynamicSharedMemorySize, SMEM1_BYTES);
    cudaFuncSetAttribute(gemm_kernel, cudaFuncAttributeMaxDynamicSharedMemorySize, SMEM2_BYTES);

    quad_kernel<<<NN / K1_COLS, 256, SMEM1_BYTES>>>(phi, theta);
    gemm_kernel<<<dim3(DD / 128, NN / 128), 256, SMEM2_BYTES>>>(c, Q, phi, out);
}

// round 3
// speedup vs baseline: 1.0042x; 1.0042x over previous
#include <cuda_runtime.h>
#include <cuda_bf16.h>
#include <math.h>

// Problem constants
#define NN 65536
#define DD 2048
#define LD 64          // d
#define SS 32          // s
#define KTRI 2080      // d*(d+1)/2
#define KTOT 96        // d + s

// Scratch: quad = theta^T @ psi, (32 x 65536) fp32 = 8 MB
__device__ float g_quad[(size_t)SS * NN];

__device__ __forceinline__ unsigned f2tf(float x) {
    unsigned y;
    asm("cvt.rna.tf32.f32 %0, %1;" : "=r"(y) : "f"(x));
    return y;
}

__device__ __forceinline__ void mma_tf32(float* c,
                                         unsigned a0, unsigned a1, unsigned a2, unsigned a3,
                                         unsigned b0, unsigned b1) {
    asm volatile(
        "mma.sync.aligned.m16n8k8.row.col.f32.tf32.tf32.f32 "
        "{%0,%1,%2,%3}, {%4,%5,%6,%7}, {%8,%9}, {%0,%1,%2,%3};"
        : "+f"(c[0]), "+f"(c[1]), "+f"(c[2]), "+f"(c[3])
        : "r"(a0), "r"(a1), "r"(a2), "r"(a3), "r"(b0), "r"(b1));
}

// ---------------------------------------------------------------------------
// Kernel 1: quad^T (Ncols x 32) = psi^T (Ncols x 2080) @ theta (2080 x 32)
// psi generated on the fly from a phi tile in smem. CTA = 8 warps x 64 cols.
// ---------------------------------------------------------------------------
#define K1_COLS 512
#define PHI_STRIDE 520     // mod 32 == 8 -> conflict-free fragment reads
#define KC 208             // K chunk (2080 = 10 * 208), 26 k-steps per chunk
#define TH_STRIDE 40       // mod 32 == 8

#define SMEM1_BYTES (((64 * PHI_STRIDE) + (KC * TH_STRIDE)) * 4 + 2 * KTRI)

__global__ __launch_bounds__(256)
void quad_kernel(const float* __restrict__ phi, const float* __restrict__ theta) {
    extern __shared__ float sm1[];
    float* phi_s = sm1;                                    // 64 * 520
    float* th_s  = sm1 + 64 * PHI_STRIDE;                  // 208 * 40 (tf32 bits)
    unsigned char* ii_s = (unsigned char*)(th_s + KC * TH_STRIDE);
    unsigned char* jj_s = ii_s + KTRI;

    const int tid  = threadIdx.x;
    const int lane = tid & 31;
    const int wid  = tid >> 5;
    const int tig  = lane & 3;   // thread in group
    const int grp  = lane >> 2;  // group id
    const int c0   = blockIdx.x * K1_COLS;

    // Build (i,j) index tables for triu ordering
    for (int k = tid; k < KTRI; k += 256) {
        int gi = (int)(64.5f - sqrtf(64.5f * 64.5f - 2.0f * (float)k));
        gi = max(0, min(63, gi));
        while (gi > 0 && (gi * 64 - (gi * (gi - 1)) / 2) > k) --gi;
        while (gi < 63 && ((gi + 1) * 64 - ((gi + 1) * gi) / 2) <= k) ++gi;
        int base = gi * 64 - (gi * (gi - 1)) / 2;
        ii_s[k] = (unsigned char)gi;
        jj_s[k] = (unsigned char)(gi + (k - base));
    }

    // Load phi tile (64 x 512) in fp32 (products rounded to tf32 later)
    for (int idx = tid; idx < 64 * (K1_COLS / 4); idx += 256) {
        int r  = idx / (K1_COLS / 4);
        int c4 = idx % (K1_COLS / 4);
        float4 v = *(const float4*)(phi + (size_t)r * NN + c0 + c4 * 4);
        float* dst = phi_s + r * PHI_STRIDE + c4 * 4;
        dst[0] = v.x; dst[1] = v.y; dst[2] = v.z; dst[3] = v.w;
    }
    __syncthreads();

    float acc[4][4][4];
#pragma unroll
    for (int a = 0; a < 4; a++)
#pragma unroll
        for (int b = 0; b < 4; b++)
#pragma unroll
            for (int q = 0; q < 4; q++) acc[a][b][q] = 0.f;

    const int wcol = wid * 64;

    for (int ch = 0; ch < KTRI / KC; ++ch) {
        const int kb = ch * KC;
        __syncthreads();  // protect th_s from previous chunk's readers
        // Stage theta chunk (208 x 32), converted to tf32
        for (int idx = tid; idx < KC * 8; idx += 256) {
            int r = idx >> 3, c4 = idx & 7;
            float4 v = *(const float4*)(theta + (size_t)(kb + r) * SS + c4 * 4);
            unsigned* dst = (unsigned*)(th_s + r * TH_STRIDE + c4 * 4);
            dst[0] = f2tf(v.x); dst[1] = f2tf(v.y); dst[2] = f2tf(v.z); dst[3] = f2tf(v.w);
        }
        __syncthreads();

        for (int ks = 0; ks < KC / 8; ++ks) {
            const int k0 = ks * 8;
            const int kg = kb + k0 + tig;
            const int i0 = ii_s[kg],     j0 = jj_s[kg];
            const int i1 = ii_s[kg + 4], j1 = jj_s[kg + 4];
            const float* pi0 = phi_s + i0 * PHI_STRIDE;
            const float* pj0 = phi_s + j0 * PHI_STRIDE;
            const float* pi1 = phi_s + i1 * PHI_STRIDE;
            const float* pj1 = phi_s + j1 * PHI_STRIDE;

            unsigned bfr[4][2];
#pragma unroll
            for (int nt = 0; nt < 4; ++nt) {
                int nB = nt * 8 + grp;
                bfr[nt][0] = __float_as_uint(th_s[(k0 + tig) * TH_STRIDE + nB]);
                bfr[nt][1] = __float_as_uint(th_s[(k0 + tig + 4) * TH_STRIDE + nB]);
            }
#pragma unroll
            for (int mt = 0; mt < 4; ++mt) {
                int col = wcol + mt * 16 + grp;
                unsigned a0 = f2tf(pi0[col]     * pj0[col]);
                unsigned a1 = f2tf(pi0[col + 8] * pj0[col + 8]);
                unsigned a2 = f2tf(pi1[col]     * pj1[col]);
                unsigned a3 = f2tf(pi1[col + 8] * pj1[col + 8]);
#pragma unroll
                for (int nt = 0; nt < 4; ++nt)
                    mma_tf32(acc[mt][nt], a0, a1, a2, a3, bfr[nt][0], bfr[nt][1]);
            }
        }
    }

    // Epilogue: C[col_local][r] -> g_quad[r][col_global]
#pragma unroll
    for (int mt = 0; mt < 4; ++mt) {
        int colg = c0 + wcol + mt * 16 + grp;
#pragma unroll
        for (int nt = 0; nt < 4; ++nt) {
            int r = nt * 8 + 2 * tig;
            g_quad[(size_t)r       * NN + colg]     = acc[mt][nt][0];
            g_quad[(size_t)(r + 1) * NN + colg]     = acc[mt][nt][1];
            g_quad[(size_t)r       * NN + colg + 8] = acc[mt][nt][2];
            g_quad[(size_t)(r + 1) * NN + colg + 8] = acc[mt][nt][3];
        }
    }
}

// ---------------------------------------------------------------------------
// Kernel 2: out (2048 x 65536) = c + Q (2048 x 96) @ z (96 x 65536)
// z rows 0..63 = phi, rows 64..95 = g_quad. CTA tile 128x128, K=96 one-shot.
// ---------------------------------------------------------------------------
#define QS_STRIDE 100   // mod 32 == 4 -> conflict-free A reads
#define BS_STRIDE 136   // mod 32 == 8 -> conflict-free B reads
#define SMEM2_BYTES ((128 * QS_STRIDE + KTOT * BS_STRIDE) * 4)

__global__ __launch_bounds__(256, 2)
void gemm_kernel(const float* __restrict__ cvec, const float* __restrict__ Q,
                 const float* __restrict__ phi, float* __restrict__ out) {
    extern __shared__ float sm2[];
    float* Qs = sm2;                       // 128 x 100 (tf32 bits)
    float* Bs = sm2 + 128 * QS_STRIDE;     // 96 x 136  (tf32 bits)

    const int tid  = threadIdx.x;
    const int lane = tid & 31;
    const int wid  = tid >> 5;
    const int tig  = lane & 3;
    const int grp  = lane >> 2;
    const int wm   = wid & 3;   // 4 warps along M
    const int wn   = wid >> 2;  // 2 warps along N
    const int m0   = blockIdx.x * 128;  // 16 m-tiles (fast dim -> z L2 reuse)
    const int n0   = blockIdx.y * 128;  // 512 n-tiles

    // Stage Q tile (128 x 96) as tf32
    for (int idx = tid; idx < 128 * 24; idx += 256) {
        int m = idx / 24, c4 = idx % 24;
        float4 v = *(const float4*)(Q + (size_t)(m0 + m) * KTOT + c4 * 4);
        unsigned* dst = (unsigned*)(Qs + m * QS_STRIDE + c4 * 4);
        dst[0] = f2tf(v.x); dst[1] = f2tf(v.y); dst[2] = f2tf(v.z); dst[3] = f2tf(v.w);
    }
    // Stage B tile (96 x 128): k<64 from phi, k>=64 from g_quad
    for (int idx = tid; idx < KTOT * 32; idx += 256) {
        int k = idx >> 5, c4 = idx & 31;
        const float* src = (k < LD) ? (phi + (size_t)k * NN)
                                    : (g_quad + (size_t)(k - LD) * NN);
        float4 v = *(const float4*)(src + n0 + c4 * 4);
        unsigned* dst = (unsigned*)(Bs + k * BS_STRIDE + c4 * 4);
        dst[0] = f2tf(v.x); dst[1] = f2tf(v.y); dst[2] = f2tf(v.z); dst[3] = f2tf(v.w);
    }
    __syncthreads();

    float acc[2][8][4];
#pragma unroll
    for (int a = 0; a < 2; a++)
#pragma unroll
        for (int b = 0; b < 8; b++)
#pragma unroll
            for (int q = 0; q < 4; q++) acc[a][b][q] = 0.f;

#pragma unroll
    for (int ks = 0; ks < 12; ++ks) {
        const int k0 = ks * 8;
        unsigned afr[2][4];
#pragma unroll
        for (int mt = 0; mt < 2; ++mt) {
            int row = wm * 32 + mt * 16 + grp;
            afr[mt][0] = __float_as_uint(Qs[row * QS_STRIDE + k0 + tig]);
            afr[mt][1] = __float_as_uint(Qs[(row + 8) * QS_STRIDE + k0 + tig]);
            afr[mt][2] = __float_as_uint(Qs[row * QS_STRIDE + k0 + tig + 4]);
            afr[mt][3] = __float_as_uint(Qs[(row + 8) * QS_STRIDE + k0 + tig + 4]);
        }
#pragma unroll
        for (int nt = 0; nt < 8; ++nt) {
            int coln = wn * 64 + nt * 8 + grp;
            unsigned b0 = __float_as_uint(Bs[(k0 + tig) * BS_STRIDE + coln]);
            unsigned b1 = __float_as_uint(Bs[(k0 + tig + 4) * BS_STRIDE + coln]);
#pragma unroll
            for (int mt = 0; mt < 2; ++mt)
                mma_tf32(acc[mt][nt], afr[mt][0], afr[mt][1], afr[mt][2], afr[mt][3], b0, b1);
        }
    }

    // Epilogue: add c[m], write fp32
#pragma unroll
    for (int mt = 0; mt < 2; ++mt) {
        int rowg = m0 + wm * 32 + mt * 16 + grp;
        float cA = __ldg(cvec + rowg);
        float cB = __ldg(cvec + rowg + 8);
#pragma unroll
        for (int nt = 0; nt < 8; ++nt) {
            int colg = n0 + wn * 64 + nt * 8 + 2 * tig;
            float2 v0 = make_float2(acc[mt][nt][0] + cA, acc[mt][nt][1] + cA);
            float2 v1 = make_float2(acc[mt][nt][2] + cB, acc[mt][nt][3] + cB);
            *(float2*)(out + (size_t)rowg * NN + colg)       = v0;
            *(float2*)(out + (size_t)(rowg + 8) * NN + colg) = v1;
        }
    }
}

// ---------------------------------------------------------------------------
extern "C" void kernel_launch(void* const* d_in, const int* in_sizes, int n_in,
                              void* d_out, int out_size) {
    const float* c     = (const float*)d_in[0];   // (2048, 1)
    const float* Q     = (const float*)d_in[1];   // (2048, 96)
    const float* phi   = (const float*)d_in[2];   // (64, 65536)
    const float* theta = (const float*)d_in[3];   // (2080, 32)
    float* out = (float*)d_out;                   // (2048, 65536)

    cudaFuncSetAttribute(quad_kernel, cudaFuncAttributeMaxDynamicSharedMemorySize, SMEM1_BYTES);
    cudaFuncSetAttribute(gemm_kernel, cudaFuncAttributeMaxDynamicSharedMemorySize, SMEM2_BYTES);

    quad_kernel<<<NN / K1_COLS, 256, SMEM1_BYTES>>>(phi, theta);
    gemm_kernel<<<dim3(DD / 128, NN / 128), 256, SMEM2_BYTES>>>(c, Q, phi, out);
}

// round 4
// speedup vs baseline: 1.5641x; 1.5576x over previous
#include <cuda_runtime.h>
#include <cuda_bf16.h>
#include <math.h>

// Problem constants
#define NN 65536
#define DD 2048
#define LD 64          // d
#define SS 32          // s
#define KTRI 2080      // d*(d+1)/2
#define KTOT 96        // d + s

// Scratch: quad (tf32 bits) and phi (tf32 bits) so the gemm hot loop has no cvt.
__device__ unsigned g_quad_t[(size_t)SS * NN];   // 8 MB
__device__ unsigned g_phi_t[(size_t)LD * NN];    // 16 MB

__device__ __forceinline__ unsigned f2tf(float x) {
    unsigned y;
    asm("cvt.rna.tf32.f32 %0, %1;" : "=r"(y) : "f"(x));
    return y;
}

__device__ __forceinline__ void mma_tf32(float* c,
                                         unsigned a0, unsigned a1, unsigned a2, unsigned a3,
                                         unsigned b0, unsigned b1) {
    asm volatile(
        "mma.sync.aligned.m16n8k8.row.col.f32.tf32.tf32.f32 "
        "{%0,%1,%2,%3}, {%4,%5,%6,%7}, {%8,%9}, {%0,%1,%2,%3};"
        : "+f"(c[0]), "+f"(c[1]), "+f"(c[2]), "+f"(c[3])
        : "r"(a0), "r"(a1), "r"(a2), "r"(a3), "r"(b0), "r"(b1));
}

// ---------------------------------------------------------------------------
// Kernel 1: quad^T (Ncols x 32) = psi^T (Ncols x 2080) @ theta (2080 x 32)
// psi generated on the fly from a phi tile in smem. Also emits g_phi_t (tf32).
// K1_COLS=256 -> 256 CTAs, 105KB smem -> 2 CTAs/SM.
// ---------------------------------------------------------------------------
#define K1_COLS 256
#define PHI_STRIDE 264     // mod 32 == 8 -> conflict-free fragment reads
#define KC 208             // K chunk (2080 = 10 * 208), 26 k-steps per chunk
#define TH_STRIDE 40       // mod 32 == 8

#define SMEM1_BYTES (((64 * PHI_STRIDE) + (KC * TH_STRIDE)) * 4 + 2 * KTRI)

__global__ __launch_bounds__(256)
void quad_kernel(const float* __restrict__ phi, const float* __restrict__ theta) {
    extern __shared__ float sm1[];
    float* phi_s = sm1;                                    // 64 * 264
    float* th_s  = sm1 + 64 * PHI_STRIDE;                  // 208 * 40 (tf32 bits)
    unsigned char* ii_s = (unsigned char*)(th_s + KC * TH_STRIDE);
    unsigned char* jj_s = ii_s + KTRI;

    const int tid  = threadIdx.x;
    const int lane = tid & 31;
    const int wid  = tid >> 5;
    const int tig  = lane & 3;   // thread in group
    const int grp  = lane >> 2;  // group id
    const int c0   = blockIdx.x * K1_COLS;

    // Build (i,j) index tables for triu ordering
    for (int k = tid; k < KTRI; k += 256) {
        int gi = (int)(64.5f - sqrtf(64.5f * 64.5f - 2.0f * (float)k));
        gi = max(0, min(63, gi));
        while (gi > 0 && (gi * 64 - (gi * (gi - 1)) / 2) > k) --gi;
        while (gi < 63 && ((gi + 1) * 64 - ((gi + 1) * gi) / 2) <= k) ++gi;
        int base = gi * 64 - (gi * (gi - 1)) / 2;
        ii_s[k] = (unsigned char)gi;
        jj_s[k] = (unsigned char)(gi + (k - base));
    }

    // Load phi tile (64 x 256) in fp32; also emit tf32 copy to g_phi_t
    for (int idx = tid; idx < 64 * (K1_COLS / 4); idx += 256) {
        int r  = idx / (K1_COLS / 4);
        int c4 = idx % (K1_COLS / 4);
        float4 v = *(const float4*)(phi + (size_t)r * NN + c0 + c4 * 4);
        float* dst = phi_s + r * PHI_STRIDE + c4 * 4;
        dst[0] = v.x; dst[1] = v.y; dst[2] = v.z; dst[3] = v.w;
        uint4 tv;
        tv.x = f2tf(v.x); tv.y = f2tf(v.y); tv.z = f2tf(v.z); tv.w = f2tf(v.w);
        *(uint4*)(g_phi_t + (size_t)r * NN + c0 + c4 * 4) = tv;
    }
    __syncthreads();

    float acc[2][4][4];
#pragma unroll
    for (int a = 0; a < 2; a++)
#pragma unroll
        for (int b = 0; b < 4; b++)
#pragma unroll
            for (int q = 0; q < 4; q++) acc[a][b][q] = 0.f;

    const int wcol = wid * 32;

    for (int ch = 0; ch < KTRI / KC; ++ch) {
        const int kb = ch * KC;
        __syncthreads();  // protect th_s from previous chunk's readers
        // Stage theta chunk (208 x 32), converted to tf32
        for (int idx = tid; idx < KC * 8; idx += 256) {
            int r = idx >> 3, c4 = idx & 7;
            float4 v = *(const float4*)(theta + (size_t)(kb + r) * SS + c4 * 4);
            unsigned* dst = (unsigned*)(th_s + r * TH_STRIDE + c4 * 4);
            dst[0] = f2tf(v.x); dst[1] = f2tf(v.y); dst[2] = f2tf(v.z); dst[3] = f2tf(v.w);
        }
        __syncthreads();

        for (int ks = 0; ks < KC / 8; ++ks) {
            const int k0 = ks * 8;
            const int kg = kb + k0 + tig;
            const int i0 = ii_s[kg],     j0 = jj_s[kg];
            const int i1 = ii_s[kg + 4], j1 = jj_s[kg + 4];
            const float* pi0 = phi_s + i0 * PHI_STRIDE;
            const float* pj0 = phi_s + j0 * PHI_STRIDE;
            const float* pi1 = phi_s + i1 * PHI_STRIDE;
            const float* pj1 = phi_s + j1 * PHI_STRIDE;

            unsigned bfr[4][2];
#pragma unroll
            for (int nt = 0; nt < 4; ++nt) {
                int nB = nt * 8 + grp;
                bfr[nt][0] = __float_as_uint(th_s[(k0 + tig) * TH_STRIDE + nB]);
                bfr[nt][1] = __float_as_uint(th_s[(k0 + tig + 4) * TH_STRIDE + nB]);
            }
#pragma unroll
            for (int mt = 0; mt < 2; ++mt) {
                int col = wcol + mt * 16 + grp;
                unsigned a0 = f2tf(pi0[col]     * pj0[col]);
                unsigned a1 = f2tf(pi0[col + 8] * pj0[col + 8]);
                unsigned a2 = f2tf(pi1[col]     * pj1[col]);
                unsigned a3 = f2tf(pi1[col + 8] * pj1[col + 8]);
#pragma unroll
                for (int nt = 0; nt < 4; ++nt)
                    mma_tf32(acc[mt][nt], a0, a1, a2, a3, bfr[nt][0], bfr[nt][1]);
            }
        }
    }

    // Epilogue: C[col_local][r] -> g_quad_t[r][col_global], tf32-rounded
#pragma unroll
    for (int mt = 0; mt < 2; ++mt) {
        int colg = c0 + wcol + mt * 16 + grp;
#pragma unroll
        for (int nt = 0; nt < 4; ++nt) {
            int r = nt * 8 + 2 * tig;
            g_quad_t[(size_t)r       * NN + colg]     = f2tf(acc[mt][nt][0]);
            g_quad_t[(size_t)(r + 1) * NN + colg]     = f2tf(acc[mt][nt][1]);
            g_quad_t[(size_t)r       * NN + colg + 8] = f2tf(acc[mt][nt][2]);
            g_quad_t[(size_t)(r + 1) * NN + colg + 8] = f2tf(acc[mt][nt][3]);
        }
    }
}

// ---------------------------------------------------------------------------
// Kernel 2: out (2048 x 65536) = c + Q (2048 x 96) @ z (96 x 65536)
// Persistent CTA: one 128-row M-tile x NT consecutive 128-col N-tiles.
// Q staged once; B double-buffered via cp.async of pre-converted tf32 bits.
// ---------------------------------------------------------------------------
#define NT 8
#define QS_STRIDE 100   // mod 32 == 4 -> conflict-free A reads
#define BS_STRIDE 136   // mod 32 == 8 -> conflict-free B reads; row = 544B (16B-aligned)
#define SMEM2_BYTES ((128 * QS_STRIDE + 2 * KTOT * BS_STRIDE) * 4)

__device__ __forceinline__ void cp_stage_B(float* Bsb, int n0, int tid) {
#pragma unroll
    for (int i = 0; i < 12; ++i) {
        int idx = i * 256 + tid;
        int k = idx >> 5, c4 = idx & 31;
        const unsigned* src = (k < LD) ? (g_phi_t + (size_t)k * NN + n0 + c4 * 4)
                                       : (g_quad_t + (size_t)(k - LD) * NN + n0 + c4 * 4);
        unsigned saddr = (unsigned)__cvta_generic_to_shared(Bsb + k * BS_STRIDE + c4 * 4);
        asm volatile("cp.async.cg.shared.global [%0], [%1], 16;\n"
                     :: "r"(saddr), "l"(src));
    }
    asm volatile("cp.async.commit_group;" ::: "memory");
}

__global__ __launch_bounds__(256, 1)
void gemm_kernel(const float* __restrict__ cvec, const float* __restrict__ Q,
                 float* __restrict__ out) {
    extern __shared__ float sm2[];
    float* Qs  = sm2;                        // 128 x 100 (tf32 bits)
    float* Bs0 = sm2 + 128 * QS_STRIDE;      // 2 x (96 x 136) tf32 bits

    const int tid  = threadIdx.x;
    const int lane = tid & 31;
    const int wid  = tid >> 5;
    const int tig  = lane & 3;
    const int grp  = lane >> 2;
    const int wm   = wid & 3;   // 4 warps along M
    const int wn   = wid >> 2;  // 2 warps along N
    const int m0   = blockIdx.x * 128;             // 16 M-tiles (fast dim)
    const int nb   = blockIdx.y * (128 * NT);      // 64 N-groups

    // Stage Q tile (128 x 96) once, as tf32
    for (int idx = tid; idx < 128 * 24; idx += 256) {
        int m = idx / 24, c4 = idx % 24;
        float4 v = *(const float4*)(Q + (size_t)(m0 + m) * KTOT + c4 * 4);
        unsigned* dst = (unsigned*)(Qs + m * QS_STRIDE + c4 * 4);
        dst[0] = f2tf(v.x); dst[1] = f2tf(v.y); dst[2] = f2tf(v.z); dst[3] = f2tf(v.w);
    }

    // Prefetch B tile 0
    cp_stage_B(Bs0, nb, tid);

    const float cA0 = __ldg(cvec + m0 + wm * 32 + grp);
    const float cB0 = __ldg(cvec + m0 + wm * 32 + grp + 8);
    const float cA1 = __ldg(cvec + m0 + wm * 32 + 16 + grp);
    const float cB1 = __ldg(cvec + m0 + wm * 32 + 16 + grp + 8);

    for (int t = 0; t < NT; ++t) {
        asm volatile("cp.async.wait_group 0;" ::: "memory");
        __syncthreads();   // tile t ready in buf t&1; buf (t+1)&1 fully consumed

        if (t + 1 < NT)
            cp_stage_B(Bs0 + ((t + 1) & 1) * KTOT * BS_STRIDE, nb + (t + 1) * 128, tid);

        const float* Bsb = Bs0 + (t & 1) * KTOT * BS_STRIDE;
        const int n0 = nb + t * 128;

        float acc[2][8][4];
#pragma unroll
        for (int a = 0; a < 2; a++)
#pragma unroll
            for (int b = 0; b < 8; b++)
#pragma unroll
                for (int q = 0; q < 4; q++) acc[a][b][q] = 0.f;

#pragma unroll
        for (int ks = 0; ks < 12; ++ks) {
            const int k0 = ks * 8;
            unsigned afr[2][4];
#pragma unroll
            for (int mt = 0; mt < 2; ++mt) {
                int row = wm * 32 + mt * 16 + grp;
                afr[mt][0] = __float_as_uint(Qs[row * QS_STRIDE + k0 + tig]);
                afr[mt][1] = __float_as_uint(Qs[(row + 8) * QS_STRIDE + k0 + tig]);
                afr[mt][2] = __float_as_uint(Qs[row * QS_STRIDE + k0 + tig + 4]);
                afr[mt][3] = __float_as_uint(Qs[(row + 8) * QS_STRIDE + k0 + tig + 4]);
            }
#pragma unroll
            for (int nt = 0; nt < 8; ++nt) {
                int coln = wn * 64 + nt * 8 + grp;
                unsigned b0 = __float_as_uint(Bsb[(k0 + tig) * BS_STRIDE + coln]);
                unsigned b1 = __float_as_uint(Bsb[(k0 + tig + 4) * BS_STRIDE + coln]);
#pragma unroll
                for (int mt = 0; mt < 2; ++mt)
                    mma_tf32(acc[mt][nt], afr[mt][0], afr[mt][1], afr[mt][2], afr[mt][3], b0, b1);
            }
        }

        // Epilogue: add c[m], write fp32
#pragma unroll
        for (int mt = 0; mt < 2; ++mt) {
            int rowg = m0 + wm * 32 + mt * 16 + grp;
            float cA = mt ? cA1 : cA0;
            float cB = mt ? cB1 : cB0;
#pragma unroll
            for (int nt = 0; nt < 8; ++nt) {
                int colg = n0 + wn * 64 + nt * 8 + 2 * tig;
                float2 v0 = make_float2(acc[mt][nt][0] + cA, acc[mt][nt][1] + cA);
                float2 v1 = make_float2(acc[mt][nt][2] + cB, acc[mt][nt][3] + cB);
                *(float2*)(out + (size_t)rowg * NN + colg)       = v0;
                *(float2*)(out + (size_t)(rowg + 8) * NN + colg) = v1;
            }
        }
    }
}

// ---------------------------------------------------------------------------
extern "C" void kernel_launch(void* const* d_in, const int* in_sizes, int n_in,
                              void* d_out, int out_size) {
    const float* c     = (const float*)d_in[0];   // (2048, 1)
    const float* Q     = (const float*)d_in[1];   // (2048, 96)
    const float* phi   = (const float*)d_in[2];   // (64, 65536)
    const float* theta = (const float*)d_in[3];   // (2080, 32)
    float* out = (float*)d_out;                   // (2048, 65536)

    cudaFuncSetAttribute(quad_kernel, cudaFuncAttributeMaxDynamicSharedMemorySize, SMEM1_BYTES);
    cudaFuncSetAttribute(gemm_kernel, cudaFuncAttributeMaxDynamicSharedMemorySize, SMEM2_BYTES);

    quad_kernel<<<NN / K1_COLS, 256, SMEM1_BYTES>>>(phi, theta);
    gemm_kernel<<<dim3(DD / 128, NN / (128 * NT)), 256, SMEM2_BYTES>>>(c, Q, out);
}

// round 5
// speedup vs baseline: 1.5870x; 1.0147x over previous
#include <cuda_runtime.h>
#include <cuda_bf16.h>
#include <math.h>

// Problem constants
#define NN 65536
#define DD 2048
#define LD 64          // d
#define SS 32          // s
#define KTRI 2080      // d*(d+1)/2
#define KTOT 96        // d + s

// Scratch: quad (tf32 bits) and phi (tf32 bits) so the gemm hot loop has no cvt.
__device__ unsigned g_quad_t[(size_t)SS * NN];   // 8 MB
__device__ unsigned g_phi_t[(size_t)LD * NN];    // 16 MB

__device__ __forceinline__ unsigned f2tf(float x) {
    unsigned y;
    asm("cvt.rna.tf32.f32 %0, %1;" : "=r"(y) : "f"(x));
    return y;
}

__device__ __forceinline__ void mma_tf32(float* c,
                                         unsigned a0, unsigned a1, unsigned a2, unsigned a3,
                                         unsigned b0, unsigned b1) {
    asm volatile(
        "mma.sync.aligned.m16n8k8.row.col.f32.tf32.tf32.f32 "
        "{%0,%1,%2,%3}, {%4,%5,%6,%7}, {%8,%9}, {%0,%1,%2,%3};"
        : "+f"(c[0]), "+f"(c[1]), "+f"(c[2]), "+f"(c[3])
        : "r"(a0), "r"(a1), "r"(a2), "r"(a3), "r"(b0), "r"(b1));
}

// ---------------------------------------------------------------------------
// Kernel 1: quad^T (Ncols x 32) = psi^T (Ncols x 2080) @ theta (2080 x 32)
// psi generated on the fly from a phi tile in smem. Also emits g_phi_t (tf32).
// K1_COLS=256 -> 256 CTAs, 105KB smem -> 2 CTAs/SM (single wave).
// ---------------------------------------------------------------------------
#define K1_COLS 256
#define PHI_STRIDE 264     // mod 32 == 8 -> conflict-free fragment reads
#define KC 208             // K chunk (2080 = 10 * 208), 26 k-steps per chunk
#define TH_STRIDE 40       // mod 32 == 8

#define SMEM1_BYTES (((64 * PHI_STRIDE) + (KC * TH_STRIDE)) * 4 + 2 * KTRI)

__global__ __launch_bounds__(256)
void quad_kernel(const float* __restrict__ phi, const float* __restrict__ theta) {
    extern __shared__ float sm1[];
    float* phi_s = sm1;                                    // 64 * 264
    float* th_s  = sm1 + 64 * PHI_STRIDE;                  // 208 * 40 (tf32 bits)
    unsigned char* ii_s = (unsigned char*)(th_s + KC * TH_STRIDE);
    unsigned char* jj_s = ii_s + KTRI;

    const int tid  = threadIdx.x;
    const int lane = tid & 31;
    const int wid  = tid >> 5;
    const int tig  = lane & 3;   // thread in group
    const int grp  = lane >> 2;  // group id
    const int c0   = blockIdx.x * K1_COLS;

    // Build (i,j) index tables for triu ordering
    for (int k = tid; k < KTRI; k += 256) {
        int gi = (int)(64.5f - sqrtf(64.5f * 64.5f - 2.0f * (float)k));
        gi = max(0, min(63, gi));
        while (gi > 0 && (gi * 64 - (gi * (gi - 1)) / 2) > k) --gi;
        while (gi < 63 && ((gi + 1) * 64 - ((gi + 1) * gi) / 2) <= k) ++gi;
        int base = gi * 64 - (gi * (gi - 1)) / 2;
        ii_s[k] = (unsigned char)gi;
        jj_s[k] = (unsigned char)(gi + (k - base));
    }

    // Load phi tile (64 x 256) in fp32; also emit tf32 copy to g_phi_t
    for (int idx = tid; idx < 64 * (K1_COLS / 4); idx += 256) {
        int r  = idx / (K1_COLS / 4);
        int c4 = idx % (K1_COLS / 4);
        float4 v = *(const float4*)(phi + (size_t)r * NN + c0 + c4 * 4);
        float* dst = phi_s + r * PHI_STRIDE + c4 * 4;
        dst[0] = v.x; dst[1] = v.y; dst[2] = v.z; dst[3] = v.w;
        uint4 tv;
        tv.x = f2tf(v.x); tv.y = f2tf(v.y); tv.z = f2tf(v.z); tv.w = f2tf(v.w);
        *(uint4*)(g_phi_t + (size_t)r * NN + c0 + c4 * 4) = tv;
    }
    __syncthreads();

    float acc[2][4][4];
#pragma unroll
    for (int a = 0; a < 2; a++)
#pragma unroll
        for (int b = 0; b < 4; b++)
#pragma unroll
            for (int q = 0; q < 4; q++) acc[a][b][q] = 0.f;

    const int wcol = wid * 32;

    for (int ch = 0; ch < KTRI / KC; ++ch) {
        const int kb = ch * KC;
        __syncthreads();  // protect th_s from previous chunk's readers
        // Stage theta chunk (208 x 32), converted to tf32
        for (int idx = tid; idx < KC * 8; idx += 256) {
            int r = idx >> 3, c4 = idx & 7;
            float4 v = *(const float4*)(theta + (size_t)(kb + r) * SS + c4 * 4);
            unsigned* dst = (unsigned*)(th_s + r * TH_STRIDE + c4 * 4);
            dst[0] = f2tf(v.x); dst[1] = f2tf(v.y); dst[2] = f2tf(v.z); dst[3] = f2tf(v.w);
        }
        __syncthreads();

#pragma unroll 2
        for (int ks = 0; ks < KC / 8; ++ks) {
            const int k0 = ks * 8;
            const int kg = kb + k0 + tig;
            const int i0 = ii_s[kg],     j0 = jj_s[kg];
            const int i1 = ii_s[kg + 4], j1 = jj_s[kg + 4];
            const float* pi0 = phi_s + i0 * PHI_STRIDE;
            const float* pj0 = phi_s + j0 * PHI_STRIDE;
            const float* pi1 = phi_s + i1 * PHI_STRIDE;
            const float* pj1 = phi_s + j1 * PHI_STRIDE;

            unsigned bfr[4][2];
#pragma unroll
            for (int nt = 0; nt < 4; ++nt) {
                int nB = nt * 8 + grp;
                bfr[nt][0] = __float_as_uint(th_s[(k0 + tig) * TH_STRIDE + nB]);
                bfr[nt][1] = __float_as_uint(th_s[(k0 + tig + 4) * TH_STRIDE + nB]);
            }
#pragma unroll
            for (int mt = 0; mt < 2; ++mt) {
                int col = wcol + mt * 16 + grp;
                unsigned a0 = f2tf(pi0[col]     * pj0[col]);
                unsigned a1 = f2tf(pi0[col + 8] * pj0[col + 8]);
                unsigned a2 = f2tf(pi1[col]     * pj1[col]);
                unsigned a3 = f2tf(pi1[col + 8] * pj1[col + 8]);
#pragma unroll
                for (int nt = 0; nt < 4; ++nt)
                    mma_tf32(acc[mt][nt], a0, a1, a2, a3, bfr[nt][0], bfr[nt][1]);
            }
        }
    }

    // Epilogue: C[col_local][r] -> g_quad_t[r][col_global], tf32-rounded
#pragma unroll
    for (int mt = 0; mt < 2; ++mt) {
        int colg = c0 + wcol + mt * 16 + grp;
#pragma unroll
        for (int nt = 0; nt < 4; ++nt) {
            int r = nt * 8 + 2 * tig;
            g_quad_t[(size_t)r       * NN + colg]     = f2tf(acc[mt][nt][0]);
            g_quad_t[(size_t)(r + 1) * NN + colg]     = f2tf(acc[mt][nt][1]);
            g_quad_t[(size_t)r       * NN + colg + 8] = f2tf(acc[mt][nt][2]);
            g_quad_t[(size_t)(r + 1) * NN + colg + 8] = f2tf(acc[mt][nt][3]);
        }
    }
}

// ---------------------------------------------------------------------------
// Kernel 2: out (2048 x 65536) = c + Q (2048 x 96) @ z (96 x 65536)
// Persistent CTA: one 128-row M-tile x NT consecutive 128-col N-tiles.
// 512 threads / 16 warps (4 per SMSP) for latency hiding; warp tile 32x32.
// Q staged once; B double-buffered via cp.async of pre-converted tf32 bits.
// ---------------------------------------------------------------------------
#define NT 8
#define QS_STRIDE 100   // mod 32 == 4 -> conflict-free A reads
#define BS_STRIDE 136   // mod 32 == 8 -> conflict-free B reads; row = 544B (16B-aligned)
#define SMEM2_BYTES ((128 * QS_STRIDE + 2 * KTOT * BS_STRIDE) * 4)

__device__ __forceinline__ void cp_stage_B(float* Bsb, int n0, int tid) {
#pragma unroll
    for (int i = 0; i < 6; ++i) {
        int idx = i * 512 + tid;
        int k = idx >> 5, c4 = idx & 31;
        const unsigned* src = (k < LD) ? (g_phi_t + (size_t)k * NN + n0 + c4 * 4)
                                       : (g_quad_t + (size_t)(k - LD) * NN + n0 + c4 * 4);
        unsigned saddr = (unsigned)__cvta_generic_to_shared(Bsb + k * BS_STRIDE + c4 * 4);
        asm volatile("cp.async.cg.shared.global [%0], [%1], 16;\n"
                     :: "r"(saddr), "l"(src));
    }
    asm volatile("cp.async.commit_group;" ::: "memory");
}

__global__ __launch_bounds__(512, 1)
void gemm_kernel(const float* __restrict__ cvec, const float* __restrict__ Q,
                 float* __restrict__ out) {
    extern __shared__ float sm2[];
    float* Qs  = sm2;                        // 128 x 100 (tf32 bits)
    float* Bs0 = sm2 + 128 * QS_STRIDE;      // 2 x (96 x 136) tf32 bits

    const int tid  = threadIdx.x;
    const int lane = tid & 31;
    const int wid  = tid >> 5;
    const int tig  = lane & 3;
    const int grp  = lane >> 2;
    const int wm   = wid & 3;   // 4 warps along M (32 rows each)
    const int wn   = wid >> 2;  // 4 warps along N (32 cols each)
    const int m0   = blockIdx.x * 128;             // 16 M-tiles (fast dim)
    const int nb   = blockIdx.y * (128 * NT);      // 64 N-groups

    // Stage Q tile (128 x 96) once, as tf32
    for (int idx = tid; idx < 128 * 24; idx += 512) {
        int m = idx / 24, c4 = idx % 24;
        float4 v = *(const float4*)(Q + (size_t)(m0 + m) * KTOT + c4 * 4);
        unsigned* dst = (unsigned*)(Qs + m * QS_STRIDE + c4 * 4);
        dst[0] = f2tf(v.x); dst[1] = f2tf(v.y); dst[2] = f2tf(v.z); dst[3] = f2tf(v.w);
    }

    // Prefetch B tile 0
    cp_stage_B(Bs0, nb, tid);

    const float cA0 = __ldg(cvec + m0 + wm * 32 + grp);
    const float cB0 = __ldg(cvec + m0 + wm * 32 + grp + 8);
    const float cA1 = __ldg(cvec + m0 + wm * 32 + 16 + grp);
    const float cB1 = __ldg(cvec + m0 + wm * 32 + 16 + grp + 8);

    for (int t = 0; t < NT; ++t) {
        asm volatile("cp.async.wait_group 0;" ::: "memory");
        __syncthreads();   // tile t ready in buf t&1; buf (t+1)&1 fully consumed

        if (t + 1 < NT)
            cp_stage_B(Bs0 + ((t + 1) & 1) * KTOT * BS_STRIDE, nb + (t + 1) * 128, tid);

        const float* Bsb = Bs0 + (t & 1) * KTOT * BS_STRIDE;
        const int n0 = nb + t * 128;

        float acc[2][4][4];
#pragma unroll
        for (int a = 0; a < 2; a++)
#pragma unroll
            for (int b = 0; b < 4; b++)
#pragma unroll
                for (int q = 0; q < 4; q++) acc[a][b][q] = 0.f;

#pragma unroll
        for (int ks = 0; ks < 12; ++ks) {
            const int k0 = ks * 8;
            unsigned afr[2][4];
#pragma unroll
            for (int mt = 0; mt < 2; ++mt) {
                int row = wm * 32 + mt * 16 + grp;
                afr[mt][0] = __float_as_uint(Qs[row * QS_STRIDE + k0 + tig]);
                afr[mt][1] = __float_as_uint(Qs[(row + 8) * QS_STRIDE + k0 + tig]);
                afr[mt][2] = __float_as_uint(Qs[row * QS_STRIDE + k0 + tig + 4]);
                afr[mt][3] = __float_as_uint(Qs[(row + 8) * QS_STRIDE + k0 + tig + 4]);
            }
#pragma unroll
            for (int nt = 0; nt < 4; ++nt) {
                int coln = wn * 32 + nt * 8 + grp;
                unsigned b0 = __float_as_uint(Bsb[(k0 + tig) * BS_STRIDE + coln]);
                unsigned b1 = __float_as_uint(Bsb[(k0 + tig + 4) * BS_STRIDE + coln]);
#pragma unroll
                for (int mt = 0; mt < 2; ++mt)
                    mma_tf32(acc[mt][nt], afr[mt][0], afr[mt][1], afr[mt][2], afr[mt][3], b0, b1);
            }
        }

        // Epilogue: add c[m], write fp32
#pragma unroll
        for (int mt = 0; mt < 2; ++mt) {
            int rowg = m0 + wm * 32 + mt * 16 + grp;
            float cA = mt ? cA1 : cA0;
            float cB = mt ? cB1 : cB0;
#pragma unroll
            for (int nt = 0; nt < 4; ++nt) {
                int colg = n0 + wn * 32 + nt * 8 + 2 * tig;
                float2 v0 = make_float2(acc[mt][nt][0] + cA, acc[mt][nt][1] + cA);
                float2 v1 = make_float2(acc[mt][nt][2] + cB, acc[mt][nt][3] + cB);
                *(float2*)(out + (size_t)rowg * NN + colg)       = v0;
                *(float2*)(out + (size_t)(rowg + 8) * NN + colg) = v1;
            }
        }
    }
}

// ---------------------------------------------------------------------------
extern "C" void kernel_launch(void* const* d_in, const int* in_sizes, int n_in,
                              void* d_out, int out_size) {
    const float* c     = (const float*)d_in[0];   // (2048, 1)
    const float* Q     = (const float*)d_in[1];   // (2048, 96)
    const float* phi   = (const float*)d_in[2];   // (64, 65536)
    const float* theta = (const float*)d_in[3];   // (2080, 32)
    float* out = (float*)d_out;                   // (2048, 65536)

    cudaFuncSetAttribute(quad_kernel, cudaFuncAttributeMaxDynamicSharedMemorySize, SMEM1_BYTES);
    cudaFuncSetAttribute(gemm_kernel, cudaFuncAttributeMaxDynamicSharedMemorySize, SMEM2_BYTES);

    quad_kernel<<<NN / K1_COLS, 256, SMEM1_BYTES>>>(phi, theta);
    gemm_kernel<<<dim3(DD / 128, NN / (128 * NT)), 512, SMEM2_BYTES>>>(c, Q, out);
}